// round 1
// baseline (speedup 1.0000x reference)
#include <cuda_runtime.h>
#include <math.h>

#define NN 50000
#define EE 1600000
#define GG 256
#define HH 128

// ---------------- scratch (static device allocations) ----------------
__device__ int   g_row[NN + 1];
__device__ int   g_col[EE];
__device__ int   g_fill[NN];
__device__ float g_deginv[NN];
__device__ float g_m [NN * HH];
__device__ float g_h1[NN * HH];
__device__ float g_h2[NN * HH];
__device__ float g_hb[NN * HH];
__device__ float g_pool[GG * 2 * HH];

// ---------------- utility kernels ----------------
__global__ void k_zero_int(int* p, int n) {
    int i = blockIdx.x * blockDim.x + threadIdx.x;
    if (i < n) p[i] = 0;
}
__global__ void k_zero_f(float* p, int n) {
    int i = blockIdx.x * blockDim.x + threadIdx.x;
    if (i < n) p[i] = 0.0f;
}

// count in-degree into g_fill
__global__ void k_count(const int* __restrict__ dst) {
    int e = blockIdx.x * blockDim.x + threadIdx.x;
    if (e < EE) atomicAdd(&g_fill[dst[e]], 1);
}

// single-block scan: counts (in g_fill) -> row starts (g_row), fill cursors (g_fill), deg_inv
__global__ void k_scan() {
    __shared__ int ssum[1024];
    int t = threadIdx.x;
    const int C = (NN + 1023) / 1024;
    int s = t * C;
    int e = s + C; if (e > NN) e = NN;
    int loc = 0;
    for (int i = s; i < e; i++) loc += g_fill[i];
    ssum[t] = loc;
    __syncthreads();
    if (t == 0) {
        int run = 0;
        for (int i = 0; i < 1024; i++) { int v = ssum[i]; ssum[i] = run; run += v; }
        g_row[NN] = run;
    }
    __syncthreads();
    int run = ssum[t];
    for (int i = s; i < e; i++) {
        int c = g_fill[i];
        g_row[i]    = run;
        g_fill[i]   = run;
        g_deginv[i] = 1.0f / fmaxf((float)c, 1.0f);
        run += c;
    }
}

// scatter src ids into CSR columns
__global__ void k_fillcsr(const int* __restrict__ src, const int* __restrict__ dst) {
    int e = blockIdx.x * blockDim.x + threadIdx.x;
    if (e < EE) {
        int pos = atomicAdd(&g_fill[dst[e]], 1);
        g_col[pos] = src[e];
    }
}

// mean aggregation: one warp per dst node, lane handles float4. Output -> g_m
__global__ void k_agg(const float* __restrict__ x) {
    int n = blockIdx.x * 8 + (threadIdx.x >> 5);
    if (n >= NN) return;
    int lane = threadIdx.x & 31;
    int s = g_row[n], e = g_row[n + 1];
    float4 acc = make_float4(0.f, 0.f, 0.f, 0.f);
    const float* xb = x + (size_t)lane * 4;
    #pragma unroll 4
    for (int i = s; i < e; i++) {
        int c = __ldg(&g_col[i]);
        float4 v = *(const float4*)(xb + (size_t)c * HH);
        acc.x += v.x; acc.y += v.y; acc.z += v.z; acc.w += v.w;
    }
    float d = g_deginv[n];
    acc.x *= d; acc.y *= d; acc.z *= d; acc.w *= d;
    *(float4*)(g_m + (size_t)n * HH + lane * 4) = acc;
}

// out = relu(A1@W1 + A2@W2 + bias); A* are [NN,128], W* are [128,128] row-major
__global__ __launch_bounds__(256) void k_gemm2relu(
    const float* __restrict__ A1, const float* __restrict__ W1,
    const float* __restrict__ A2, const float* __restrict__ W2,
    const float* __restrict__ bias, float* __restrict__ out)
{
    __shared__ float As[8][128];
    __shared__ float Bs[8][128];
    int tid = threadIdx.x;
    int tx = tid & 15, ty = tid >> 4;
    int m0 = blockIdx.x * 128;

    float acc[8][8];
    #pragma unroll
    for (int i = 0; i < 8; i++)
        #pragma unroll
        for (int j = 0; j < 8; j++) acc[i][j] = 0.0f;

    int lrow = tid >> 1, lhalf = tid & 1;
    int wr = tid >> 5, wc = (tid & 31) * 4;

    #pragma unroll
    for (int p = 0; p < 2; p++) {
        const float* A = p ? A2 : A1;
        const float* W = p ? W2 : W1;
        for (int k0 = 0; k0 < 128; k0 += 8) {
            __syncthreads();
            int gr = m0 + lrow; if (gr >= NN) gr = NN - 1;
            float4 av = *(const float4*)(A + (size_t)gr * 128 + k0 + lhalf * 4);
            As[lhalf * 4 + 0][lrow] = av.x;
            As[lhalf * 4 + 1][lrow] = av.y;
            As[lhalf * 4 + 2][lrow] = av.z;
            As[lhalf * 4 + 3][lrow] = av.w;
            *(float4*)&Bs[wr][wc] = *(const float4*)(W + (size_t)(k0 + wr) * 128 + wc);
            __syncthreads();
            #pragma unroll
            for (int k = 0; k < 8; k++) {
                float a[8], b[8];
                #pragma unroll
                for (int i = 0; i < 8; i++) a[i] = As[k][ty * 8 + i];
                #pragma unroll
                for (int j = 0; j < 8; j++) b[j] = Bs[k][tx * 8 + j];
                #pragma unroll
                for (int i = 0; i < 8; i++)
                    #pragma unroll
                    for (int j = 0; j < 8; j++)
                        acc[i][j] += a[i] * b[j];
            }
        }
    }

    float bj[8];
    #pragma unroll
    for (int j = 0; j < 8; j++) bj[j] = bias[tx * 8 + j];
    #pragma unroll
    for (int i = 0; i < 8; i++) {
        int r = m0 + ty * 8 + i;
        if (r < NN) {
            float4 v0, v1;
            v0.x = fmaxf(acc[i][0] + bj[0], 0.f);
            v0.y = fmaxf(acc[i][1] + bj[1], 0.f);
            v0.z = fmaxf(acc[i][2] + bj[2], 0.f);
            v0.w = fmaxf(acc[i][3] + bj[3], 0.f);
            v1.x = fmaxf(acc[i][4] + bj[4], 0.f);
            v1.y = fmaxf(acc[i][5] + bj[5], 0.f);
            v1.z = fmaxf(acc[i][6] + bj[6], 0.f);
            v1.w = fmaxf(acc[i][7] + bj[7], 0.f);
            float* op = out + (size_t)r * 128 + tx * 8;
            *(float4*)(op)     = v0;
            *(float4*)(op + 4) = v1;
        }
    }
}

// segment pool: atomicAdd rows of h into g_pool[batch[n]*256 + off ...]
__global__ void k_pool(const float* __restrict__ h, const int* __restrict__ batch, int off) {
    int idx = blockIdx.x * blockDim.x + threadIdx.x;
    int n = idx >> 5;
    if (n >= NN) return;
    int lane = idx & 31;
    int b = batch[n];
    float4 v = *(const float4*)(h + (size_t)n * 128 + lane * 4);
    float* p = g_pool + (size_t)b * 256 + off + lane * 4;
    atomicAdd(p + 0, v.x);
    atomicAdd(p + 1, v.y);
    atomicAdd(p + 2, v.z);
    atomicAdd(p + 3, v.w);
}

// head: BN + lin1(256->128)+relu + lin2(128->10) + softmax. one block per graph.
__global__ void k_head(const float* __restrict__ gamma, const float* __restrict__ beta,
                       const float* __restrict__ rm, const float* __restrict__ rv,
                       const float* __restrict__ W1, const float* __restrict__ b1,
                       const float* __restrict__ W2, const float* __restrict__ b2,
                       float* __restrict__ out)
{
    __shared__ float sg[256];
    __shared__ float s1[128];
    __shared__ float s2[10];
    int g = blockIdx.x, t = threadIdx.x;  // 128 threads
    for (int i = t; i < 256; i += 128) {
        float v = g_pool[g * 256 + i];
        v = (v - rm[i]) * rsqrtf(rv[i] + 1e-5f) * gamma[i] + beta[i];
        sg[i] = v;
    }
    __syncthreads();
    float acc = b1[t];
    #pragma unroll 8
    for (int k = 0; k < 256; k++) acc += sg[k] * W1[k * 128 + t];
    s1[t] = fmaxf(acc, 0.f);
    __syncthreads();
    if (t < 10) {
        float a = b2[t];
        #pragma unroll 8
        for (int k = 0; k < 128; k++) a += s1[k] * W2[k * 10 + t];
        s2[t] = a;
    }
    __syncthreads();
    if (t == 0) {
        float m = s2[0];
        for (int j = 1; j < 10; j++) m = fmaxf(m, s2[j]);
        float ex[10]; float sum = 0.f;
        for (int j = 0; j < 10; j++) { ex[j] = expf(s2[j] - m); sum += ex[j]; }
        float inv = 1.0f / sum;
        for (int j = 0; j < 10; j++) out[g * 10 + j] = ex[j] * inv;
    }
}

// ---------------- host launch ----------------
extern "C" void kernel_launch(void* const* d_in, const int* in_sizes, int n_in,
                              void* d_out, int out_size)
{
    const float* x     = (const float*)d_in[0];
    const int*   ei    = (const int*)d_in[1];
    const int*   batch = (const int*)d_in[2];
    // num_graphs may or may not be materialized as an input
    int base = (n_in > 3 && in_sizes[3] == 1) ? 4 : 3;

    const float* p[24];
    for (int i = 0; i < 24; i++) p[i] = (const float*)d_in[base + i];
    // b0: 0..7  (Wl1, Wr1, b1, Wl2, Wr2, b2, Wlin, blin)
    // b1: 8..15
    // bn_gamma 16, bn_beta 17, bn_rm 18, bn_rv 19, lin1_W 20, lin1_b 21, lin2_W 22, lin2_b 23

    const int* src = ei;
    const int* dst = ei + EE;

    void *pm, *ph1, *ph2, *phb, *pfill, *ppool;
    cudaGetSymbolAddress(&pm,   g_m);
    cudaGetSymbolAddress(&ph1,  g_h1);
    cudaGetSymbolAddress(&ph2,  g_h2);
    cudaGetSymbolAddress(&phb,  g_hb);
    cudaGetSymbolAddress(&pfill, g_fill);
    cudaGetSymbolAddress(&ppool, g_pool);

    float* fm  = (float*)pm;
    float* fh1 = (float*)ph1;
    float* fh2 = (float*)ph2;
    float* fhb = (float*)phb;

    const int ZB = 256;
    // ---- CSR build ----
    k_zero_int<<<(NN + ZB - 1) / ZB, ZB>>>((int*)pfill, NN);
    k_count<<<(EE + ZB - 1) / ZB, ZB>>>(dst);
    k_scan<<<1, 1024>>>();
    k_fillcsr<<<(EE + ZB - 1) / ZB, ZB>>>(src, dst);

    const int AGG_BLOCKS  = (NN + 7) / 8;
    const int GEMM_BLOCKS = (NN + 127) / 128;
    const int POOL_BLOCKS = (NN * 32 + ZB - 1) / ZB;

    // ---- block 0 ----
    k_agg<<<AGG_BLOCKS, 256>>>(x);
    k_gemm2relu<<<GEMM_BLOCKS, 256>>>(fm, p[0], x, p[1], p[2], fh1);
    k_agg<<<AGG_BLOCKS, 256>>>(fh1);
    k_gemm2relu<<<GEMM_BLOCKS, 256>>>(fm, p[3], fh1, p[4], p[5], fh2);
    k_gemm2relu<<<GEMM_BLOCKS, 256>>>(fh1, p[6], fh2, p[6] + 128 * 128, p[7], fhb);

    // ---- pool 0 ----
    k_zero_f<<<(GG * 256 + ZB - 1) / ZB, ZB>>>((float*)ppool, GG * 256);
    k_pool<<<POOL_BLOCKS, ZB>>>(fhb, batch, 0);

    // ---- block 1 ----
    k_agg<<<AGG_BLOCKS, 256>>>(fhb);
    k_gemm2relu<<<GEMM_BLOCKS, 256>>>(fm, p[8], fhb, p[9], p[10], fh1);
    k_agg<<<AGG_BLOCKS, 256>>>(fh1);
    k_gemm2relu<<<GEMM_BLOCKS, 256>>>(fm, p[11], fh1, p[12], p[13], fh2);
    k_gemm2relu<<<GEMM_BLOCKS, 256>>>(fh1, p[14], fh2, p[14] + 128 * 128, p[15], fm);

    // ---- pool 1 ----
    k_pool<<<POOL_BLOCKS, ZB>>>(fm, batch, 128);

    // ---- head ----
    k_head<<<GG, 128>>>(p[16], p[17], p[18], p[19], p[20], p[21], p[22], p[23],
                        (float*)d_out);
}